// round 15
// baseline (speedup 1.0000x reference)
#include <cuda_runtime.h>
#include <math.h>

// FPN ROIAlign pooler (maskrcnn-benchmark semantics, non-aligned).
// f0:[2,256,200,304] f1:[2,256,100,152] f2:[2,256,50,76] f3:[2,256,25,38]
// boxes:[N,4] xyxy, box_batch_idx:[N] -> out:[N,256,7,7] fp32
//
// Strategy:
//  - prep_kernel: per-box level mapping + ROI params -> __device__ scratch.
//  - pool_kernel: one thread per (box, channel-group of 8, output pixel).
//    Tap coordinates/bilinear weights computed once, applied to 8 channels
//    (64 independent gathers per thread for deep MLP). Warp lanes sweep the
//    49 pixels of one (box, cgroup) so the small ROI footprint stays L1-hot.

#define OUTP 7
#define NPIX (OUTP * OUTP)
#define NCH 256
#define CG 8
#define GROUPS (NCH / CG)
#define MAXN 4096

__device__ float g_bp[MAXN * 4];  // x1s, y1s, bin_w, bin_h (feature coords)
__device__ int   g_bm[MAXN * 2];  // level (0..3), batch index

__global__ void prep_kernel(const float* __restrict__ boxes,
                            const int* __restrict__ bidx, int N) {
    int i = blockIdx.x * blockDim.x + threadIdx.x;
    if (i >= N) return;
    float x1 = boxes[i * 4 + 0];
    float y1 = boxes[i * 4 + 1];
    float x2 = boxes[i * 4 + 2];
    float y2 = boxes[i * 4 + 3];
    // level mapping: floor(4 + log2(sqrt(area)/224 + 1e-6)), clip [2,5], -2
    float s = sqrtf((x2 - x1 + 1.0f) * (y2 - y1 + 1.0f));
    float lvlf = floorf(4.0f + log2f(s / 224.0f + 1e-6f));
    lvlf = fminf(fmaxf(lvlf, 2.0f), 5.0f);
    int lvl = (int)lvlf - 2;
    float scale = 0.25f / (float)(1 << lvl);
    float x1s = x1 * scale;
    float y1s = y1 * scale;
    float rw = fmaxf(x2 * scale - x1s, 1.0f);
    float rh = fmaxf(y2 * scale - y1s, 1.0f);
    g_bp[i * 4 + 0] = x1s;
    g_bp[i * 4 + 1] = y1s;
    g_bp[i * 4 + 2] = rw * (1.0f / OUTP);
    g_bp[i * 4 + 3] = rh * (1.0f / OUTP);
    g_bm[i * 2 + 0] = lvl;
    g_bm[i * 2 + 1] = bidx[i];
}

__global__ void __launch_bounds__(256, 4) pool_kernel(
    const float* __restrict__ f0, const float* __restrict__ f1,
    const float* __restrict__ f2, const float* __restrict__ f3,
    float* __restrict__ out, int N) {
    int idx = blockIdx.x * blockDim.x + threadIdx.x;
    int total = N * NPIX * GROUPS;
    if (idx >= total) return;

    int p  = idx % NPIX;
    int cg = (idx / NPIX) % GROUPS;
    int n  = idx / (NPIX * GROUPS);
    int ph = p / OUTP;
    int pw = p - ph * OUTP;

    float x1s = g_bp[n * 4 + 0];
    float y1s = g_bp[n * 4 + 1];
    float bw  = g_bp[n * 4 + 2];
    float bh  = g_bp[n * 4 + 3];
    int lvl = g_bm[n * 2 + 0];
    int b   = g_bm[n * 2 + 1];

    const float* feat;
    int H, W;
    if (lvl == 0)      { feat = f0; H = 200; W = 304; }
    else if (lvl == 1) { feat = f1; H = 100; W = 152; }
    else if (lvl == 2) { feat = f2; H = 50;  W = 76;  }
    else               { feat = f3; H = 25;  W = 38;  }
    const int HW = H * W;
    const float* base = feat + (size_t)(b * NCH + cg * CG) * (size_t)HW;

    float acc[CG];
#pragma unroll
    for (int j = 0; j < CG; j++) acc[j] = 0.0f;

#pragma unroll
    for (int s = 0; s < 4; s++) {
        int iy = s >> 1;
        int ix = s & 1;
        // sample position (SR=2): bin start + (sub + 0.5)/SR within bin
        float y = y1s + bh * ((float)ph + 0.25f + 0.5f * (float)iy);
        float x = x1s + bw * ((float)pw + 0.25f + 0.5f * (float)ix);
        bool valid = (y >= -1.0f) && (y <= (float)H) &&
                     (x >= -1.0f) && (x <= (float)W);
        float yc = fminf(fmaxf(y, 0.0f), (float)(H - 1));
        float xc = fminf(fmaxf(x, 0.0f), (float)(W - 1));
        int y0 = (int)floorf(yc);
        int x0 = (int)floorf(xc);
        int y1i = min(y0 + 1, H - 1);
        int x1i = min(x0 + 1, W - 1);
        float ly = yc - (float)y0;
        float lx = xc - (float)x0;
        float hy = 1.0f - ly;
        float hx = 1.0f - lx;
        // fold the /4 sample average into the weights; zero if invalid
        float vmul = valid ? 0.25f : 0.0f;
        float w00 = hy * hx * vmul;
        float w01 = hy * lx * vmul;
        float w10 = ly * hx * vmul;
        float w11 = ly * lx * vmul;
        int o00 = y0 * W + x0;
        int o01 = y0 * W + x1i;
        int o10 = y1i * W + x0;
        int o11 = y1i * W + x1i;
#pragma unroll
        for (int j = 0; j < CG; j++) {
            const float* fp = base + j * HW;
            float v = w00 * __ldg(fp + o00) + w01 * __ldg(fp + o01) +
                      w10 * __ldg(fp + o10) + w11 * __ldg(fp + o11);
            acc[j] += v;
        }
    }

    size_t ob = ((size_t)n * NCH + (size_t)cg * CG) * NPIX + (size_t)p;
#pragma unroll
    for (int j = 0; j < CG; j++) out[ob + (size_t)j * NPIX] = acc[j];
}

extern "C" void kernel_launch(void* const* d_in, const int* in_sizes, int n_in,
                              void* d_out, int out_size) {
    const float* f0 = (const float*)d_in[0];
    const float* f1 = (const float*)d_in[1];
    const float* f2 = (const float*)d_in[2];
    const float* f3 = (const float*)d_in[3];
    const float* boxes = (const float*)d_in[4];
    const int* bidx = (const int*)d_in[5];
    float* out = (float*)d_out;

    int N = in_sizes[4] / 4;
    if (N > MAXN) N = MAXN;

    prep_kernel<<<(N + 255) / 256, 256>>>(boxes, bidx, N);

    int total = N * NPIX * GROUPS;
    pool_kernel<<<(total + 255) / 256, 256>>>(f0, f1, f2, f3, out, N);
}